// round 10
// baseline (speedup 1.0000x reference)
#include <cuda_runtime.h>
#include <math_constants.h>

// WeightedChamferDistance: B=4, N=M=8192, D=3.
// out = mean_b( sum_n min_m d2 * w[b,n] ) + mean_b( sum_m min_n d2 )
//
// Algorithmic round: exact NN with 1-D binned pruning. Each cloud (8 total:
// 4 src + 4 tgt) is counting-sorted into 512 x-bins, stored preprocessed as
// (-2x,-2y,-2z,|o|^2). Each query scans its home bin then expands left/right
// rings, pruning a side once (distance-to-bin-edge)^2 > current best d2.
// Expected candidates per query ~10x fewer than the 8192 brute force.
// Determinism: scatter order within a bin is atomic-order-dependent, but only
// an exact (order-invariant) min is taken over bin contents; all float SUMS
// run over queries in original order -> bit-deterministic output.

#define BATCH  4
#define NPTS   8192
#define NCLD   8                 // clouds: 0..3 = src batches, 4..7 = tgt
#define NBINS  512
#define XMIN   (-5.0f)
#define XW     (10.0f / (float)NBINS)
#define INVW   ((float)NBINS / 10.0f)

__device__ int    g_cnt[NCLD * NBINS];
__device__ int    g_cur[NCLD * NBINS];
__device__ int    g_off[NCLD * (NBINS + 1)];
__device__ float4 g_od[NCLD * NPTS];       // scattered others, preprocessed
__device__ float  g_sums[256];

__global__ void k_init()
{
    const int i = blockIdx.x * blockDim.x + threadIdx.x;
    if (i < NCLD * NBINS) g_cnt[i] = 0;
}

__device__ __forceinline__ const float* cloud_pt(const float* src, const float* tgt,
                                                 int c, int i)
{
    return (c < BATCH) ? (src + ((size_t)c * NPTS + i) * 3)
                       : (tgt + ((size_t)(c - BATCH) * NPTS + i) * 3);
}

__device__ __forceinline__ int bin_of(float x)
{
    int b = (int)((x - XMIN) * INVW);
    return min(max(b, 0), NBINS - 1);
}

__global__ void k_hist(const float* __restrict__ src, const float* __restrict__ tgt)
{
    const int id = blockIdx.x * blockDim.x + threadIdx.x;   // 0..65535
    const int c = id >> 13, i = id & (NPTS - 1);
    const float x = cloud_pt(src, tgt, c, i)[0];
    atomicAdd(&g_cnt[c * NBINS + bin_of(x)], 1);
}

__global__ __launch_bounds__(NBINS)
void k_prefix()
{
    __shared__ int sa[NBINS], sb[NBINS];
    const int t = threadIdx.x;
    for (int c = 0; c < NCLD; ++c) {
        sa[t] = g_cnt[c * NBINS + t];
        __syncthreads();
        int* in = sa;
        int* out = sb;
        #pragma unroll
        for (int s = 1; s < NBINS; s <<= 1) {
            out[t] = (t >= s) ? (in[t] + in[t - s]) : in[t];
            __syncthreads();
            int* tmp = in; in = out; out = tmp;
        }
        const int excl = (t == 0) ? 0 : in[t - 1];
        g_off[c * (NBINS + 1) + t] = excl;
        g_cur[c * NBINS + t] = excl;
        if (t == NBINS - 1) g_off[c * (NBINS + 1) + NBINS] = in[NBINS - 1];
        __syncthreads();
    }
}

__global__ void k_scatter(const float* __restrict__ src, const float* __restrict__ tgt)
{
    const int id = blockIdx.x * blockDim.x + threadIdx.x;
    const int c = id >> 13, i = id & (NPTS - 1);
    const float* p = cloud_pt(src, tgt, c, i);
    const float x = p[0], y = p[1], z = p[2];
    const int pos = atomicAdd(&g_cur[c * NBINS + bin_of(x)], 1);
    g_od[(size_t)c * NPTS + pos] =
        make_float4(-2.0f * x, -2.0f * y, -2.0f * z, x * x + y * y + z * z);
}

__device__ __forceinline__ float scan_bin(const float4* __restrict__ od,
                                          const int* __restrict__ off,
                                          int b, float qx, float qy, float qz,
                                          float best)
{
    const int s = off[b], e = off[b + 1];
    for (int j = s; j < e; ++j) {
        const float4 v = __ldg(&od[j]);
        float dd = fmaf(qx, v.x, v.w);
        dd = fmaf(qy, v.y, dd);
        dd = fmaf(qz, v.z, dd);
        best = fminf(best, dd);
    }
    return best;
}

__global__ __launch_bounds__(256)
void k_query(const float* __restrict__ src, const float* __restrict__ tgt,
             const float* __restrict__ w)
{
    __shared__ float s_red[256];

    const int id = blockIdx.x * blockDim.x + threadIdx.x;   // 0..65535
    const int c = id >> 13, i = id & (NPTS - 1);
    const float* p = cloud_pt(src, tgt, c, i);
    const float qw = (c < BATCH) ? w[(size_t)c * NPTS + i] : 1.0f;
    const float qx = p[0], qy = p[1], qz = p[2];
    const float p2 = qx * qx + qy * qy + qz * qz;

    const int o = c ^ BATCH;                    // opposite cloud
    const float4* od = g_od + (size_t)o * NPTS;
    const int* off = g_off + o * (NBINS + 1);

    float best = CUDART_INF_F;                  // accumulates min(o2 - 2 p.o)
    const int b0 = bin_of(qx);

    best = scan_bin(od, off, b0, qx, qy, qz, best);

    for (int k = 1; k < NBINS; ++k) {
        bool any = false;
        const int br = b0 + k;
        if (br < NBINS) {
            const float dx = (XMIN + (float)br * XW) - qx;   // dist to left edge
            if (dx * dx <= best + p2) {
                any = true;
                best = scan_bin(od, off, br, qx, qy, qz, best);
            }
        }
        const int bl = b0 - k;
        if (bl >= 0) {
            const float dx = qx - (XMIN + (float)(bl + 1) * XW); // dist to right edge
            if (dx * dx <= best + p2) {
                any = true;
                best = scan_bin(od, off, bl, qx, qy, qz, best);
            }
        }
        if (!any) break;
    }

    const float contrib = (best + p2) * qw;

    s_red[threadIdx.x] = contrib;
    __syncthreads();
    #pragma unroll
    for (int s = 128; s > 0; s >>= 1) {
        if (threadIdx.x < s) s_red[threadIdx.x] += s_red[threadIdx.x + s];
        __syncthreads();
    }
    if (threadIdx.x == 0) g_sums[blockIdx.x] = s_red[0];
}

__global__ void k_final(float* __restrict__ out)
{
    __shared__ float s_red[256];
    s_red[threadIdx.x] = g_sums[threadIdx.x];
    __syncthreads();
    #pragma unroll
    for (int s = 128; s > 0; s >>= 1) {
        if (threadIdx.x < s) s_red[threadIdx.x] += s_red[threadIdx.x + s];
        __syncthreads();
    }
    if (threadIdx.x == 0) out[0] = s_red[0] * (1.0f / (float)BATCH);
}

extern "C" void kernel_launch(void* const* d_in, const int* in_sizes, int n_in,
                              void* d_out, int out_size)
{
    const float* src = (const float*)d_in[0];   // [B, N, 3]
    const float* tgt = (const float*)d_in[1];   // [B, M, 3]
    const float* w   = (const float*)d_in[2];   // [B, N]
    float* out = (float*)d_out;

    k_init<<<(NCLD * NBINS + 255) / 256, 256>>>();
    k_hist<<<NCLD * NPTS / 256, 256>>>(src, tgt);
    k_prefix<<<1, NBINS>>>();
    k_scatter<<<NCLD * NPTS / 256, 256>>>(src, tgt);
    k_query<<<NCLD * NPTS / 256, 256>>>(src, tgt, w);
    k_final<<<1, 256>>>(out);
}

// round 11
// speedup vs baseline: 1.8331x; 1.8331x over previous
#include <cuda_runtime.h>
#include <math_constants.h>

// WeightedChamferDistance: B=4, N=M=8192, D=3.
// out = mean_b( sum_n min_m d2 * w[b,n] ) + mean_b( sum_m min_n d2 )
//
// Exact NN via x-sorted clouds + block-cooperative window scan:
//  - counting-sort all 8 clouds (4 src + 4 tgt) into 512 x-bins; store
//    preprocessed float4 (-2x,-2y,-2z,|o|^2) + original index.
//  - k_query: one block = 128 x-adjacent sorted queries of cloud c. Block
//    scans shared 128-candidate tiles of sorted cloud c^4 (brute-force-style
//    packed-pair FFMA2 inner loop, broadcast LDS, no divergence), expanding
//    left/right one tile at a time until every thread's bound
//    (max(0,dx_edge))^2 > best_d2 prunes that side (__syncthreads_count).
//  - contributions written by ORIGINAL index, reduced in fixed order ->
//    deterministic (scatter order inside a bin only feeds an exact min).

#define BATCH  4
#define NPTS   8192
#define NCLD   8                 // 0..3 = src batches, 4..7 = tgt batches
#define NBINS  512
#define XMIN   (-5.0f)
#define XW     (10.0f / (float)NBINS)
#define INVW   ((float)NBINS / 10.0f)
#define QT     128               // queries (=threads) per k_query block

__device__ int    g_cnt[NCLD * NBINS];
__device__ int    g_cur[NCLD * NBINS];
__device__ int    g_off[NCLD * (NBINS + 1)];
__device__ float4 g_od[NCLD * NPTS];       // sorted, preprocessed
__device__ int    g_idx[NCLD * NPTS];      // original index of sorted entry
__device__ float  g_contrib[NCLD * NPTS];
__device__ float  g_sums[256];

__global__ void k_init()
{
    const int i = blockIdx.x * blockDim.x + threadIdx.x;
    if (i < NCLD * NBINS) g_cnt[i] = 0;
}

__device__ __forceinline__ const float* cloud_pt(const float* src, const float* tgt,
                                                 int c, int i)
{
    return (c < BATCH) ? (src + ((size_t)c * NPTS + i) * 3)
                       : (tgt + ((size_t)(c - BATCH) * NPTS + i) * 3);
}

__device__ __forceinline__ int bin_of(float x)
{
    int b = (int)((x - XMIN) * INVW);
    return min(max(b, 0), NBINS - 1);
}

__global__ void k_hist(const float* __restrict__ src, const float* __restrict__ tgt)
{
    const int id = blockIdx.x * blockDim.x + threadIdx.x;   // 0..65535
    const int c = id >> 13, i = id & (NPTS - 1);
    const float x = cloud_pt(src, tgt, c, i)[0];
    atomicAdd(&g_cnt[c * NBINS + bin_of(x)], 1);
}

__global__ __launch_bounds__(NBINS)
void k_prefix()
{
    __shared__ int sa[NBINS], sb[NBINS];
    const int t = threadIdx.x;
    for (int c = 0; c < NCLD; ++c) {
        sa[t] = g_cnt[c * NBINS + t];
        __syncthreads();
        int* in = sa;
        int* out = sb;
        #pragma unroll
        for (int s = 1; s < NBINS; s <<= 1) {
            out[t] = (t >= s) ? (in[t] + in[t - s]) : in[t];
            __syncthreads();
            int* tmp = in; in = out; out = tmp;
        }
        const int excl = (t == 0) ? 0 : in[t - 1];
        g_off[c * (NBINS + 1) + t] = excl;
        g_cur[c * NBINS + t] = excl;
        if (t == NBINS - 1) g_off[c * (NBINS + 1) + NBINS] = in[NBINS - 1];
        __syncthreads();
    }
}

__global__ void k_scatter(const float* __restrict__ src, const float* __restrict__ tgt)
{
    const int id = blockIdx.x * blockDim.x + threadIdx.x;
    const int c = id >> 13, i = id & (NPTS - 1);
    const float* p = cloud_pt(src, tgt, c, i);
    const float x = p[0], y = p[1], z = p[2];
    const int pos = atomicAdd(&g_cur[c * NBINS + bin_of(x)], 1);
    g_od[(size_t)c * NPTS + pos] =
        make_float4(-2.0f * x, -2.0f * y, -2.0f * z, x * x + y * y + z * z);
    g_idx[(size_t)c * NPTS + pos] = i;
}

// Scan one <=128-candidate tile through shared (pair layout) for this
// thread's single query. Block-uniform; contains __syncthreads.
__device__ __forceinline__ void tile_scan(
    const float4* __restrict__ od, int base, int cnt,
    float* s_tile, unsigned sbase,
    unsigned long long qxx, unsigned long long qyy, unsigned long long qzz,
    float& m0, float& m1)
{
    __syncthreads();
    {
        const int j = threadIdx.x;
        const float4 v = (j < cnt) ? __ldg(&od[base + j])
                                   : make_float4(0.0f, 0.0f, 0.0f, CUDART_INF_F);
        float* bp = s_tile + (j >> 1) * 8 + (j & 1);
        bp[0] = v.x; bp[2] = v.y; bp[4] = v.z; bp[6] = v.w;
    }
    __syncthreads();
    #pragma unroll 8
    for (int kk = 0; kk < QT / 2; ++kk) {
        const unsigned a = sbase + kk * 32u;
        unsigned long long txp, typ, tzp, t2p, acc;
        asm("ld.shared.v2.u64 {%0,%1},[%2];" : "=l"(txp), "=l"(typ) : "r"(a));
        asm("ld.shared.v2.u64 {%0,%1},[%2];" : "=l"(tzp), "=l"(t2p) : "r"(a + 16u));
        asm("fma.rn.f32x2 %0,%1,%2,%3;" : "=l"(acc) : "l"(qxx), "l"(txp), "l"(t2p));
        asm("fma.rn.f32x2 %0,%1,%2,%3;" : "=l"(acc) : "l"(qyy), "l"(typ), "l"(acc));
        asm("fma.rn.f32x2 %0,%1,%2,%3;" : "=l"(acc) : "l"(qzz), "l"(tzp), "l"(acc));
        float lo, hi;
        asm("mov.b64 {%0,%1},%2;" : "=f"(lo), "=f"(hi) : "l"(acc));
        m0 = fminf(m0, lo);
        m1 = fminf(m1, hi);
    }
}

__global__ __launch_bounds__(QT)
void k_query(const float* __restrict__ w)
{
    __shared__ float s_tile[(QT / 2) * 8];
    __shared__ int   s_win[2];
    __shared__ float s_edge[2];

    const int c    = blockIdx.x >> 6;            // 64 blocks per cloud
    const int q0   = (blockIdx.x & 63) * QT;
    const int qpos = q0 + threadIdx.x;

    const float4 qr = g_od[(size_t)c * NPTS + qpos];
    const float qx = -0.5f * qr.x, qy = -0.5f * qr.y, qz = -0.5f * qr.z;
    const float p2 = qr.w;
    const int orig = g_idx[(size_t)c * NPTS + qpos];
    const float qw = (c < BATCH) ? w[(size_t)c * NPTS + orig] : 1.0f;

    unsigned long long qxx, qyy, qzz;
    asm("mov.b64 %0,{%1,%1};" : "=l"(qxx) : "f"(qx));
    asm("mov.b64 %0,{%1,%1};" : "=l"(qyy) : "f"(qy));
    asm("mov.b64 %0,{%1,%1};" : "=l"(qzz) : "f"(qz));

    const int o = c ^ BATCH;
    const float4* od = g_od + (size_t)o * NPTS;
    const int* off = g_off + o * (NBINS + 1);

    unsigned sbase;
    asm("{ .reg .u64 t; cvta.to.shared.u64 t, %1; cvt.u32.u64 %0, t; }"
        : "=r"(sbase) : "l"(s_tile));

    if (threadIdx.x == 0) {
        const float x0 = -0.5f * g_od[(size_t)c * NPTS + q0].x;
        const float x1 = -0.5f * g_od[(size_t)c * NPTS + q0 + QT - 1].x;
        s_win[0] = off[bin_of(x0)];
        s_win[1] = off[bin_of(x1) + 1];
    }
    __syncthreads();
    int lo = s_win[0], hi = s_win[1];

    float m0 = CUDART_INF_F, m1 = CUDART_INF_F;

    // Initial window (bins spanning the block's query x-range)
    for (int base = lo; base < hi; base += QT)
        tile_scan(od, base, min(QT, hi - base), s_tile, sbase, qxx, qyy, qzz, m0, m1);

    // Ring expansion with per-thread pruning, block-voted
    for (;;) {
        if (threadIdx.x == 0) {
            s_edge[0] = (lo > 0)    ? -0.5f * od[lo - 1].x : 0.0f;
            s_edge[1] = (hi < NPTS) ? -0.5f * od[hi].x     : 0.0f;
        }
        __syncthreads();
        const float d2cur = fminf(m0, m1) + p2;
        bool nL = (lo > 0);
        if (nL) { const float dx = fmaxf(qx - s_edge[0], 0.0f); nL = dx * dx <= d2cur; }
        bool nR = (hi < NPTS);
        if (nR) { const float dx = fmaxf(s_edge[1] - qx, 0.0f); nR = dx * dx <= d2cur; }
        const int cL = __syncthreads_count(nL);
        const int cR = __syncthreads_count(nR);
        if (cL == 0 && cR == 0) break;
        if (cL) {
            const int nb = max(lo - QT, 0);
            tile_scan(od, nb, lo - nb, s_tile, sbase, qxx, qyy, qzz, m0, m1);
            lo = nb;
        }
        if (cR) {
            const int ne = min(hi + QT, NPTS);
            tile_scan(od, hi, ne - hi, s_tile, sbase, qxx, qyy, qzz, m0, m1);
            hi = ne;
        }
    }

    g_contrib[(size_t)c * NPTS + orig] = (fminf(m0, m1) + p2) * qw;
}

__global__ __launch_bounds__(256)
void k_sum1()
{
    __shared__ float s_red[256];
    const int q = blockIdx.x * 256 + threadIdx.x;
    s_red[threadIdx.x] = g_contrib[q];
    __syncthreads();
    #pragma unroll
    for (int s = 128; s > 0; s >>= 1) {
        if (threadIdx.x < s) s_red[threadIdx.x] += s_red[threadIdx.x + s];
        __syncthreads();
    }
    if (threadIdx.x == 0) g_sums[blockIdx.x] = s_red[0];
}

__global__ void k_final(float* __restrict__ out)
{
    __shared__ float s_red[256];
    s_red[threadIdx.x] = g_sums[threadIdx.x];
    __syncthreads();
    #pragma unroll
    for (int s = 128; s > 0; s >>= 1) {
        if (threadIdx.x < s) s_red[threadIdx.x] += s_red[threadIdx.x + s];
        __syncthreads();
    }
    if (threadIdx.x == 0) out[0] = s_red[0] * (1.0f / (float)BATCH);
}

extern "C" void kernel_launch(void* const* d_in, const int* in_sizes, int n_in,
                              void* d_out, int out_size)
{
    const float* src = (const float*)d_in[0];   // [B, N, 3]
    const float* tgt = (const float*)d_in[1];   // [B, M, 3]
    const float* w   = (const float*)d_in[2];   // [B, N]
    float* out = (float*)d_out;

    k_init<<<(NCLD * NBINS + 255) / 256, 256>>>();
    k_hist<<<NCLD * NPTS / 256, 256>>>(src, tgt);
    k_prefix<<<1, NBINS>>>();
    k_scatter<<<NCLD * NPTS / 256, 256>>>(src, tgt);
    k_query<<<NCLD * (NPTS / QT), QT>>>(w);
    k_sum1<<<256, 256>>>();
    k_final<<<1, 256>>>(out);
}